// round 1
// baseline (speedup 1.0000x reference)
#include <cuda_runtime.h>
#include <float.h>

// ConsensusAttention: b=8, n=1024 (32x32 grid), l=6, d=512, fp32.
// Mask = grid distance > 3  =>  each query attends to <= 29 fixed neighbors.
// We compute only those 29 dot products per query (exact: masked softmax
// entries are exactly 0 in the reference), normalizing the key side by
// 1/max(||v||,1e-12) and scaling by d^-0.5.

namespace {
constexpr int kB  = 8;
constexpr int kL  = 6;
constexpr int kHW = 32;
constexpr int kN  = kHW * kHW;   // 1024
constexpr int kD  = 512;
constexpr int kDC = 64;          // d-chunk (floats)
constexpr int kNC = kD / kDC;    // 8 chunks
constexpr int kQR = 4;           // query patch-rows per block
constexpr int kQN = kQR * kHW;   // 128 queries per block
constexpr int kKRmax = kQR + 6;  // key patch-rows (max)
constexpr int kKNmax = kKRmax * kHW;  // 320 keys (max)
constexpr int kVS = 68;          // smem row stride (floats): 64 + 4 pad
constexpr int kNB = 29;          // neighbors within radius 3
constexpr int kT  = 256;         // threads per block
constexpr int kRow = kL * kD;    // global row stride (floats) = 3072
constexpr float kScale = 0.04419417382415922f;  // 512^-0.5

constexpr int kSmemBytes =
    (kKNmax * kVS + kNB * kQN + kKNmax) * 4 + kNB * kQN * 2;  // 110592

__constant__ int c_dh[kNB] = { -3,
  -2,-2,-2,-2,-2,   -1,-1,-1,-1,-1,
   0, 0, 0, 0, 0, 0, 0,
   1, 1, 1, 1, 1,    2, 2, 2, 2, 2,   3 };
__constant__ int c_dw[kNB] = {  0,
  -2,-1, 0, 1, 2,   -2,-1, 0, 1, 2,
  -3,-2,-1, 0, 1, 2, 3,
  -2,-1, 0, 1, 2,   -2,-1, 0, 1, 2,   0 };
}  // namespace

__global__ void __launch_bounds__(kT, 2)
consensus_kernel(const float* __restrict__ levels, float* __restrict__ out)
{
    extern __shared__ float smem[];
    float* vbuf = smem;                              // [kKNmax][kVS]
    float* dots = vbuf + kKNmax * kVS;               // [kNB][kQN]
    float* sqn  = dots + kNB * kQN;                  // [kKNmax]
    unsigned short* slotb =
        reinterpret_cast<unsigned short*>(sqn + kKNmax);  // [kNB][kQN]

    const int ht = blockIdx.x;   // 0..7
    const int l  = blockIdx.y;   // 0..5
    const int b  = blockIdx.z;   // 0..7
    const int h0 = ht * kQR;
    const int kr0 = max(0, h0 - 3);
    const int kr1 = min(kHW - 1, h0 + kQR - 1 + 3);
    const int kn  = (kr1 - kr0 + 1) * kHW;           // valid key slots
    const int t   = threadIdx.x;

    const float* base  = levels + ((size_t)(b * kN + kr0 * kHW) * kL + l) * kD;
    float*       obase = out    + ((size_t)(b * kN + h0  * kHW) * kL + l) * kD;

    for (int i = t; i < kKNmax; i += kT) sqn[i] = 0.f;

    // ---- pass-1 thread mapping: thread = (query, half of neighbor list) ----
    const int q    = t & (kQN - 1);
    const int half = t >> 7;              // warps 0-3: nbs 0..14; warps 4-7: 15..28
    const int nb0  = half ? 15 : 0;
    const int nk   = half ? 14 : 15;
    const int qh   = h0 + (q >> 5);
    const int qw   = q & 31;
    const int qb17 = ((qh - kr0) * kHW + qw) * 17;   // float4 index of query row

    int slt17[15];
#pragma unroll
    for (int k = 0; k < 15; k++) {
        int nb = nb0 + k; if (nb >= kNB) nb = 0;     // k==14,half==1: unused
        const int hh = qh + c_dh[nb], ww = qw + c_dw[nb];
        const bool v = (hh >= 0) & (hh < kHW) & (ww >= 0) & (ww < kHW) & (k < nk);
        slt17[k] = v ? ((hh - kr0) * kHW + ww) * 17 : 0;
    }
    float acc[15];
#pragma unroll
    for (int k = 0; k < 15; k++) acc[k] = 0.f;

    float4* vb4 = reinterpret_cast<float4*>(vbuf);

    // =========================== PASS 1: dots + ||k||^2 ===========================
    for (int c = 0; c < kNC; c++) {
        __syncthreads();  // previous chunk fully consumed
        const float* src = base + c * kDC;
        for (int idx = t; idx < kn * 16; idx += kT) {
            const int s = idx >> 4, u = idx & 15;
            vb4[s * 17 + u] =
                *reinterpret_cast<const float4*>(src + (size_t)s * kRow + (u << 2));
        }
        __syncthreads();

        // squared-norm partials
        for (int s = t; s < kn; s += kT) {
            float a = 0.f;
#pragma unroll 4
            for (int u = 0; u < 16; u++) {
                const float4 v = vb4[s * 17 + u];
                a += v.x * v.x + v.y * v.y + v.z * v.z + v.w * v.w;
            }
            sqn[s] += a;
        }

        // dot partials: q chunk streamed as float4, v rows via conflict-free LDS.128
#pragma unroll 2
        for (int f = 0; f < 16; f++) {
            const float4 qf = vb4[qb17 + f];
#pragma unroll
            for (int k = 0; k < 15; k++) {
                if (k < nk) {
                    const float4 vf = vb4[slt17[k] + f];
                    acc[k] += qf.x * vf.x + qf.y * vf.y + qf.z * vf.z + qf.w * vf.w;
                }
            }
        }
    }

#pragma unroll
    for (int k = 0; k < 15; k++)
        if (k < nk) dots[(nb0 + k) * kQN + q] = acc[k];
    __syncthreads();

    // =========================== SOFTMAX (one thread per query) ===========================
    if (t < kQN) {
        float sv[kNB];
        float smax = -FLT_MAX;
#pragma unroll
        for (int nb = 0; nb < kNB; nb++) {
            const int hh = qh + c_dh[nb], ww = qw + c_dw[nb];
            const bool v = (hh >= 0) & (hh < kHW) & (ww >= 0) & (ww < kHW);
            const int slot = v ? (hh - kr0) * kHW + ww : 0;
            slotb[nb * kQN + t] = (unsigned short)slot;
            float s;
            if (v) {
                const float rn = 1.f / fmaxf(sqrtf(sqn[slot]), 1e-12f);
                s = dots[nb * kQN + t] * rn * kScale;
            } else {
                s = -FLT_MAX;   // masked: exp underflows to exactly 0
            }
            sv[nb] = s;
            smax = fmaxf(smax, s);
        }
        float sum = 0.f;
#pragma unroll
        for (int nb = 0; nb < kNB; nb++) {
            const float p = __expf(sv[nb] - smax);
            sv[nb] = p;
            sum += p;
        }
        const float rs = 1.f / sum;   // self-neighbor always valid -> sum >= 1
#pragma unroll
        for (int nb = 0; nb < kNB; nb++)
            dots[nb * kQN + t] = sv[nb] * rs;
    }

    // =========================== PASS 2: out = P * V ===========================
    const int w = t >> 5, lane = t & 31;
    for (int c = 0; c < kNC; c++) {
        __syncthreads();  // c==0: also publishes softmax results
        const float* src = base + c * kDC;
        for (int idx = t; idx < kn * 16; idx += kT) {
            const int s = idx >> 4, u = idx & 15;
            vb4[s * 17 + u] =
                *reinterpret_cast<const float4*>(src + (size_t)s * kRow + (u << 2));
        }
        __syncthreads();

        for (int qq = w; qq < kQN; qq += 8) {
            float a0 = 0.f, a1 = 0.f;
#pragma unroll
            for (int nb = 0; nb < kNB; nb++) {
                const float p = dots[nb * kQN + qq];
                const float* vr = vbuf + (int)slotb[nb * kQN + qq] * kVS;
                a0 += p * vr[lane];        // broadcast slot, consecutive lanes
                a1 += p * vr[lane + 32];
            }
            float* op = obase + (size_t)qq * kRow + c * kDC;
            op[lane]      = a0;
            op[lane + 32] = a1;
        }
    }
}

extern "C" void kernel_launch(void* const* d_in, const int* in_sizes, int n_in,
                              void* d_out, int out_size)
{
    const float* levels = (const float*)d_in[0];
    // d_in[1] (non_local_mask) is a pure function of the fixed 32x32 geometry;
    // derived analytically in-kernel.
    float* out = (float*)d_out;

    cudaFuncSetAttribute(consensus_kernel,
                         cudaFuncAttributeMaxDynamicSharedMemorySize, kSmemBytes);
    dim3 grid(kHW / kQR, kL, kB);   // (8, 6, 8) = 384 blocks
    consensus_kernel<<<grid, kT, kSmemBytes>>>(levels, out);
}

// round 2
// speedup vs baseline: 1.4419x; 1.4419x over previous
#include <cuda_runtime.h>
#include <float.h>

// ConsensusAttention: b=8, n=1024 (32x32 grid), l=6, d=512, fp32.
// Mask = grid distance > 3  =>  29 neighbors per query.
// Round-2 structure:
//   K1: symmetric pair dots (14 positive offsets; each dot yields TWO directed
//       scores) + ||q||^2 (which IS the self dot). f32x2 packed FMA.
//       Writes raw dots to g_dots[bl][nb][q] and 1/max(||q||,eps) to g_rn.
//   K2: softmax from scratch (applies key-side normalizer + scale + mask)
//       then out = P*V with float4 lanes + f32x2 FMA.

namespace {
constexpr int kHW = 32;
constexpr int kN  = kHW * kHW;   // 1024
constexpr int kL  = 6;
constexpr int kB  = 8;
constexpr int kD  = 512;
constexpr int kDC = 64;          // d-chunk floats
constexpr int kNC = kD / kDC;    // 8
constexpr int kQR = 4;           // query patch-rows per block
constexpr int kQN = kQR * kHW;   // 128
constexpr int kVS = 68;          // smem slot stride in floats (17 float4, odd)
constexpr int kRow = kL * kD;    // 3072
constexpr int kBL = kB * kL;     // 48
constexpr float kScale = 0.04419417382415922f;  // 512^-0.5

constexpr int kKN1 = 7 * kHW;    // 224 key slots (rows h0..h0+6)
constexpr int kSmem1 = kKN1 * kVS * 4;                       // 60928 B

constexpr int kKN2 = 10 * kHW;   // 320 key slots (rows h0-3..h0+6)
constexpr int kSmem2 = kKN2 * kVS * 4   // vbuf
                     + kQN * 32 * 4     // probs [128][32]
                     + kKN2 * 4         // rns
                     + 29 * kQN * 2;    // slotb  => 112128 B

__constant__ int c_dh[29] = { -3,
  -2,-2,-2,-2,-2,   -1,-1,-1,-1,-1,
   0, 0, 0, 0, 0, 0, 0,
   1, 1, 1, 1, 1,    2, 2, 2, 2, 2,   3 };
__constant__ int c_dw[29] = {  0,
  -2,-1, 0, 1, 2,   -2,-1, 0, 1, 2,
  -3,-2,-1, 0, 1, 2, 3,
  -2,-1, 0, 1, 2,   -2,-1, 0, 1, 2,   0 };
// nb 14 = (0,0) self; nb i and 28-i are opposite offsets.
}  // namespace

__device__ float g_dots[kBL][32][kN];   // [b*l][nb][q]   raw dots
__device__ float g_rn[kBL][kN];         // 1/max(||v||, 1e-12)

__device__ __forceinline__ void fma2(unsigned long long& acc,
                                     unsigned long long a,
                                     unsigned long long b) {
    asm("fma.rn.f32x2 %0, %1, %2, %0;" : "+l"(acc) : "l"(a), "l"(b));
}
__device__ __forceinline__ unsigned long long pk2(float p) {
    unsigned long long r;
    asm("mov.b64 %0, {%1, %1};" : "=l"(r) : "f"(p));
    return r;
}
__device__ __forceinline__ float2 up2(unsigned long long v) {
    float2 r;
    asm("mov.b64 {%0, %1}, %2;" : "=f"(r.x), "=f"(r.y) : "l"(v));
    return r;
}

// ============================ Kernel 1: dots + norms ============================
__global__ void __launch_bounds__(256, 3)
k1_scores(const float* __restrict__ levels)
{
    extern __shared__ float smem[];
    float4* vb4 = reinterpret_cast<float4*>(smem);
    const ulonglong2* vbu = reinterpret_cast<const ulonglong2*>(smem);

    const int ht = blockIdx.x, l = blockIdx.y, b = blockIdx.z;
    const int h0 = ht * kQR;
    const int rows = min(kHW - 1, h0 + 6) - h0 + 1;
    const int kn = rows * kHW;
    const int t = threadIdx.x;

    const float* base = levels + ((size_t)((b * kN + h0 * kHW) * kL + l)) * kD;

    const int q = t & 127, half = t >> 7;
    const int qh = h0 + (q >> 5), qw = q & 31;
    const int nb0 = 15 + half * 7;   // half0: nbs 15..21, half1: 22..28

    int ka[7];     // clamped smem f4 base addresses
    bool kv[7];    // validity
#pragma unroll
    for (int k = 0; k < 7; k++) {
        const int dh = c_dh[nb0 + k], dw = c_dw[nb0 + k];
        const int hh = qh + dh, ww = qw + dw;
        kv[k] = (hh < kHW) & (ww >= 0) & (ww < kHW);
        const int hc = min(hh, kHW - 1);
        const int wc = min(max(ww, 0), kHW - 1);
        ka[k] = ((hc - h0) * kHW + wc) * 17;
    }

    unsigned long long acc[7];
#pragma unroll
    for (int k = 0; k < 7; k++) acc[k] = 0ull;
    unsigned long long sq = 0ull;

    for (int c = 0; c < kNC; c++) {
        __syncthreads();
        const float* src = base + c * kDC;
        for (int idx = t; idx < kn * 16; idx += 256) {
            const int s = idx >> 4, u = idx & 15;
            vb4[s * 17 + u] =
                *reinterpret_cast<const float4*>(src + (size_t)s * kRow + (u << 2));
        }
        __syncthreads();

#pragma unroll
        for (int f = 0; f < 16; f++) {
            const ulonglong2 qf = vbu[q * 17 + f];
            if (half == 0) { fma2(sq, qf.x, qf.x); fma2(sq, qf.y, qf.y); }
#pragma unroll
            for (int k = 0; k < 7; k++) {
                const ulonglong2 vf = vbu[ka[k] + f];
                fma2(acc[k], qf.x, vf.x);
                fma2(acc[k], qf.y, vf.y);
            }
        }
    }

    const int bl = b * kL + l;
    const int qglob = qh * kHW + qw;
#pragma unroll
    for (int k = 0; k < 7; k++) {
        if (kv[k]) {
            const float2 a = up2(acc[k]);
            const float d = a.x + a.y;
            const int nb = nb0 + k;
            const int jglob = (qh + c_dh[nb]) * kHW + (qw + c_dw[nb]);
            g_dots[bl][nb][qglob]      = d;   // forward score (q, +off)
            g_dots[bl][28 - nb][jglob] = d;   // backward score (q+off, -off)
        }
    }
    if (half == 0) {
        const float2 s2 = up2(sq);
        const float sqn = s2.x + s2.y;
        g_dots[bl][14][qglob] = sqn;          // self dot = ||q||^2
        g_rn[bl][qglob] = 1.f / fmaxf(sqrtf(sqn), 1e-12f);
    }
}

// ======================= Kernel 2: softmax + out = P*V =======================
__global__ void __launch_bounds__(256, 2)
k2_out(const float* __restrict__ levels, float* __restrict__ out)
{
    extern __shared__ float smem[];
    float4* vb4 = reinterpret_cast<float4*>(smem);
    const ulonglong2* vbu = reinterpret_cast<const ulonglong2*>(smem);
    float* probs = smem + kKN2 * kVS;                       // [128][32]
    float* rns   = probs + kQN * 32;                        // [320]
    unsigned short* slotb =
        reinterpret_cast<unsigned short*>(rns + kKN2);      // [29][128]

    const int ht = blockIdx.x, l = blockIdx.y, b = blockIdx.z;
    const int h0 = ht * kQR;
    const int kr0 = max(0, h0 - 3);
    const int kr1 = min(kHW - 1, h0 + 6);
    const int kn = (kr1 - kr0 + 1) * kHW;
    const int t = threadIdx.x;
    const int bl = b * kL + l;

    const float* base = levels + ((size_t)((b * kN + kr0 * kHW) * kL + l)) * kD;
    float*      obase = out    + ((size_t)((b * kN + h0  * kHW) * kL + l)) * kD;

    for (int i = t; i < kn; i += 256) rns[i] = g_rn[bl][kr0 * kHW + i];
    __syncthreads();

    if (t < kQN) {
        const int qh = h0 + (t >> 5), qw = t & 31;
        const int qglob = qh * kHW + qw;
        float sv[29];
        float smax = -FLT_MAX;
#pragma unroll
        for (int nb = 0; nb < 29; nb++) {
            const int hh = qh + c_dh[nb], ww = qw + c_dw[nb];
            const bool v = (hh >= 0) & (hh < kHW) & (ww >= 0) & (ww < kHW);
            const int slot = v ? (hh - kr0) * kHW + ww : 0;
            slotb[nb * kQN + t] = (unsigned short)slot;
            float s = -FLT_MAX;
            if (v) s = g_dots[bl][nb][qglob] * rns[slot] * kScale;
            sv[nb] = s;
            smax = fmaxf(smax, s);
        }
        float sum = 0.f;
#pragma unroll
        for (int nb = 0; nb < 29; nb++) {
            const float p = __expf(sv[nb] - smax);
            sv[nb] = p;
            sum += p;
        }
        const float rs = 1.f / sum;
#pragma unroll
        for (int nb = 0; nb < 29; nb++) probs[t * 32 + nb] = sv[nb] * rs;
        probs[t * 32 + 29] = 0.f;
        probs[t * 32 + 30] = 0.f;
        probs[t * 32 + 31] = 0.f;
    }

    // pass 2: warp handles 2 queries at a time; lanes 0..15 -> q0, 16..31 -> q1
    const int w = t >> 5, lane = t & 31;
    const int sub = lane >> 4;      // which query of the pair
    const int part = lane & 15;     // float4 index within the 64-float chunk

    for (int c = 0; c < kNC; c++) {
        __syncthreads();   // c==0 also publishes probs/slotb
        const float* src = base + c * kDC;
        for (int idx = t; idx < kn * 16; idx += 256) {
            const int s = idx >> 4, u = idx & 15;
            vb4[s * 17 + u] =
                *reinterpret_cast<const float4*>(src + (size_t)s * kRow + (u << 2));
        }
        __syncthreads();

#pragma unroll 1
        for (int qi = 0; qi < 8; qi++) {
            const int myq = w * 16 + qi * 2 + sub;
            unsigned long long ax = 0ull, ay = 0ull;
#pragma unroll
            for (int nb = 0; nb < 29; nb++) {
                const float p = probs[myq * 32 + nb];
                const int slot = (int)slotb[nb * kQN + myq];
                const ulonglong2 v = vbu[slot * 17 + part];
                const unsigned long long p2 = pk2(p);
                fma2(ax, p2, v.x);
                fma2(ay, p2, v.y);
            }
            const float2 a0 = up2(ax), a1 = up2(ay);
            float4 o; o.x = a0.x; o.y = a0.y; o.z = a1.x; o.w = a1.y;
            *reinterpret_cast<float4*>(obase + (size_t)myq * kRow + c * kDC + part * 4) = o;
        }
    }
}

extern "C" void kernel_launch(void* const* d_in, const int* in_sizes, int n_in,
                              void* d_out, int out_size)
{
    const float* levels = (const float*)d_in[0];
    // d_in[1] (non_local_mask) is a pure function of the fixed 32x32 geometry.
    float* out = (float*)d_out;

    cudaFuncSetAttribute(k1_scores,
                         cudaFuncAttributeMaxDynamicSharedMemorySize, kSmem1);
    cudaFuncSetAttribute(k2_out,
                         cudaFuncAttributeMaxDynamicSharedMemorySize, kSmem2);

    dim3 grid(kHW / kQR, kL, kB);   // (8, 6, 8)
    k1_scores<<<grid, 256, kSmem1>>>(levels);
    k2_out<<<grid, 256, kSmem2>>>(levels, out);
}

// round 4
// speedup vs baseline: 1.6350x; 1.1339x over previous
#include <cuda_runtime.h>
#include <float.h>

// ConsensusAttention: b=8, n=1024 (32x32 grid), l=6, d=512, fp32.
// K1: symmetric pair dots (14 positive offsets, each yields 2 directed scores)
//     + ||q||^2 (self dot). Writes g_dots / g_rn.
// K2: softmax (mask analytic, p==0 exact for masked) then key-stationary
//     out = P*V: each key row loaded once per warp, probs delivered by shfl
//     from a per-lane register cache. Fully unrolled stencil -> all register
//     indices compile-time.

namespace {
constexpr int kHW = 32;
constexpr int kN  = kHW * kHW;   // 1024
constexpr int kL  = 6;
constexpr int kB  = 8;
constexpr int kD  = 512;
constexpr int kDC = 64;          // d-chunk floats
constexpr int kNC = kD / kDC;    // 8
constexpr int kQR = 4;           // query patch-rows per block
constexpr int kQN = kQR * kHW;   // 128
constexpr int kRow = kL * kD;    // 3072
constexpr int kBL = kB * kL;     // 48
constexpr float kScale = 0.04419417382415922f;  // 512^-0.5

// ---- K1 ----
constexpr int kKN1 = 7 * kHW;    // 224 key slots
constexpr int kVS1 = 68;         // 17 float4
constexpr int kSmem1 = kKN1 * kVS1 * 4;   // 60928 B

// ---- K2 ----
constexpr int kKN2 = 10 * kHW;   // 320 key slots
constexpr int kVS2 = 66;         // floats per slot (33 u64) -> LDS.64 conflict-free
constexpr int kPS  = 33;         // probs row stride (floats)
constexpr int kSmem2 = (kKN2 * kVS2 + kQN * kPS + kKN2) * 4;  // 102656 B

__constant__ int c_dh[29] = { -3,
  -2,-2,-2,-2,-2,   -1,-1,-1,-1,-1,
   0, 0, 0, 0, 0, 0, 0,
   1, 1, 1, 1, 1,    2, 2, 2, 2, 2,   3 };
__constant__ int c_dw[29] = {  0,
  -2,-1, 0, 1, 2,   -2,-1, 0, 1, 2,
  -3,-2,-1, 0, 1, 2, 3,
  -2,-1, 0, 1, 2,   -2,-1, 0, 1, 2,   0 };

// stencil tables as constexpr host+device functions (fold at compile time
// inside fully-unrolled loops)
__host__ __device__ constexpr int nbBase(int r) {
    return r == 0 ? 0 : r == 1 ? 1 : r == 2 ? 6 : r == 3 ? 11
         : r == 4 ? 18 : r == 5 ? 23 : 28;
}
__host__ __device__ constexpr int dwMin(int r) {
    return (r == 0 || r == 6) ? 0 : (r == 3 ? -3 : -2);
}
__host__ __device__ constexpr int dwMax(int r) {
    return (r == 0 || r == 6) ? 0 : (r == 3 ? 3 : 2);
}
}  // namespace

__device__ float g_dots[kBL][32][kN];   // [b*l][nb][q]  raw dots
__device__ float g_rn[kBL][kN];         // 1/max(||v||,1e-12)

__device__ __forceinline__ void fma2(unsigned long long& acc,
                                     unsigned long long a,
                                     unsigned long long b) {
    asm("fma.rn.f32x2 %0, %1, %2, %0;" : "+l"(acc) : "l"(a), "l"(b));
}
__device__ __forceinline__ unsigned long long pk2(float p) {
    unsigned long long r;
    asm("mov.b64 %0, {%1, %1};" : "=l"(r) : "f"(p));
    return r;
}
__device__ __forceinline__ float2 up2(unsigned long long v) {
    float2 r;
    asm("mov.b64 {%0, %1}, %2;" : "=f"(r.x), "=f"(r.y) : "l"(v));
    return r;
}

// ============================ Kernel 1: dots + norms ============================
__global__ void __launch_bounds__(256, 3)
k1_scores(const float* __restrict__ levels)
{
    extern __shared__ float smem[];
    float4* vb4 = reinterpret_cast<float4*>(smem);
    const ulonglong2* vbu = reinterpret_cast<const ulonglong2*>(smem);

    const int ht = blockIdx.x, l = blockIdx.y, b = blockIdx.z;
    const int h0 = ht * kQR;
    const int rows = min(kHW - 1, h0 + 6) - h0 + 1;
    const int kn = rows * kHW;
    const int t = threadIdx.x;

    const float* base = levels + ((size_t)((b * kN + h0 * kHW) * kL + l)) * kD;

    const int q = t & 127, half = t >> 7;
    const int qh = h0 + (q >> 5), qw = q & 31;
    const int nb0 = 15 + half * 7;   // half0: nbs 15..21, half1: 22..28

    int ka[7];
    bool kv[7];
#pragma unroll
    for (int k = 0; k < 7; k++) {
        const int dh = c_dh[nb0 + k], dw = c_dw[nb0 + k];
        const int hh = qh + dh, ww = qw + dw;
        kv[k] = (hh < kHW) & (ww >= 0) & (ww < kHW);
        const int hc = min(hh, kHW - 1);
        const int wc = min(max(ww, 0), kHW - 1);
        ka[k] = ((hc - h0) * kHW + wc) * 17;
    }

    unsigned long long acc[7];
#pragma unroll
    for (int k = 0; k < 7; k++) acc[k] = 0ull;
    unsigned long long sq = 0ull;

    for (int c = 0; c < kNC; c++) {
        __syncthreads();
        const float* src = base + c * kDC;
        for (int idx = t; idx < kn * 16; idx += 256) {
            const int s = idx >> 4, u = idx & 15;
            vb4[s * 17 + u] =
                *reinterpret_cast<const float4*>(src + (size_t)s * kRow + (u << 2));
        }
        __syncthreads();

#pragma unroll
        for (int f = 0; f < 16; f++) {
            const ulonglong2 qf = vbu[q * 17 + f];
            if (half == 0) { fma2(sq, qf.x, qf.x); fma2(sq, qf.y, qf.y); }
#pragma unroll
            for (int k = 0; k < 7; k++) {
                const ulonglong2 vf = vbu[ka[k] + f];
                fma2(acc[k], qf.x, vf.x);
                fma2(acc[k], qf.y, vf.y);
            }
        }
    }

    const int bl = b * kL + l;
    const int qglob = qh * kHW + qw;
#pragma unroll
    for (int k = 0; k < 7; k++) {
        if (kv[k]) {
            const float2 a = up2(acc[k]);
            const float d = a.x + a.y;
            const int nb = nb0 + k;
            const int jglob = (qh + c_dh[nb]) * kHW + (qw + c_dw[nb]);
            g_dots[bl][nb][qglob]      = d;
            g_dots[bl][28 - nb][jglob] = d;
        }
    }
    if (half == 0) {
        const float2 s2 = up2(sq);
        const float sqn = s2.x + s2.y;
        g_dots[bl][14][qglob] = sqn;      // self dot = ||q||^2
        g_rn[bl][qglob] = 1.f / fmaxf(sqrtf(sqn), 1e-12f);
    }
}

// ======================= Kernel 2: softmax + key-stationary P*V =======================
__global__ void __launch_bounds__(256, 2)
k2_out(const float* __restrict__ levels, float* __restrict__ out)
{
    extern __shared__ float smem[];
    float* vbuf  = smem;                         // [320][66]
    float* probs = vbuf + kKN2 * kVS2;           // [128][33]
    float* rns   = probs + kQN * kPS;            // [320]
    unsigned long long* vbu = reinterpret_cast<unsigned long long*>(vbuf);

    const int ht = blockIdx.x, l = blockIdx.y, b = blockIdx.z;
    const int h0 = ht * kQR;
    const int kr0 = max(0, h0 - 3);
    const int kr1 = min(kHW - 1, h0 + 6);
    const int kn = (kr1 - kr0 + 1) * kHW;
    const int t = threadIdx.x;
    const int bl = b * kL + l;

    const float* base = levels + ((size_t)((b * kN + kr0 * kHW) * kL + l)) * kD;
    float*      obase = out    + ((size_t)((b * kN + h0  * kHW) * kL + l)) * kD;

    for (int i = t; i < kn; i += 256) rns[i] = g_rn[bl][kr0 * kHW + i];
    __syncthreads();

    // ---------------- softmax: one thread per query ----------------
    if (t < kQN) {
        const int qh = h0 + (t >> 5), qw = t & 31;
        const int qglob = qh * kHW + qw;
        float sv[29];
        float smax = -FLT_MAX;
#pragma unroll
        for (int nb = 0; nb < 29; nb++) {
            const int hh = qh + c_dh[nb], ww = qw + c_dw[nb];
            const bool v = (hh >= 0) & (hh < kHW) & (ww >= 0) & (ww < kHW);
            const int slot = v ? (hh - kr0) * kHW + ww : 0;
            float s = -FLT_MAX;
            if (v) s = g_dots[bl][nb][qglob] * rns[slot] * kScale;
            sv[nb] = s;
            smax = fmaxf(smax, s);
        }
        float sum = 0.f;
#pragma unroll
        for (int nb = 0; nb < 29; nb++) {
            const float p = __expf(sv[nb] - smax);  // masked -> exactly 0
            sv[nb] = p;
            sum += p;
        }
        const float rs = 1.f / sum;
#pragma unroll
        for (int nb = 0; nb < 29; nb++) probs[t * kPS + nb] = sv[nb] * rs;
    }

    // ---------------- key-stationary P*V ----------------
    // warp = (query patch-row, 16-query half); lane = d-pair within 64-float chunk
    const int wid = t >> 5, lane = t & 31;
    const int qrow = wid >> 1;            // 0..3
    const int qbase = (wid & 1) * 16;     // 0 or 16
    const int qh = h0 + qrow;

    // per-key smem base indices (u64 units), compile-time indexable arrays
    int rowb[7];
#pragma unroll
    for (int r = 0; r < 7; r++) {
        const int hh = min(max(qh + (r - 3), 0), kHW - 1);
        rowb[r] = (hh - kr0) * kHW * (kVS2 / 2);
    }
    int colb[22];
#pragma unroll
    for (int j = 0; j < 22; j++) {
        const int ww = min(max(qbase - 3 + j, 0), kHW - 1);
        colb[j] = ww * (kVS2 / 2);
    }

    float preg[29];

    for (int c = 0; c < kNC; c++) {
        __syncthreads();   // vbuf reusable; (c==0) probs published
        const float* src = base + c * kDC;
        for (int idx = t; idx < kn * 16; idx += 256) {
            const int s = idx >> 4, u = idx & 15;
            const float4 v =
                *reinterpret_cast<const float4*>(src + (size_t)s * kRow + (u << 2));
            unsigned long long* dst = vbu + s * (kVS2 / 2) + u * 2;
            float2 lo; lo.x = v.x; lo.y = v.y;
            float2 hi; hi.x = v.z; hi.y = v.w;
            dst[0] = *reinterpret_cast<unsigned long long*>(&lo);
            dst[1] = *reinterpret_cast<unsigned long long*>(&hi);
        }
        __syncthreads();

        if (c == 0) {
            const int qloc = qrow * kHW + qbase + (lane & 15);
#pragma unroll
            for (int nb = 0; nb < 29; nb++)
                preg[nb] = probs[qloc * kPS + nb];
        }

        unsigned long long acc[16];
#pragma unroll
        for (int qi = 0; qi < 16; qi++) acc[qi] = 0ull;

#pragma unroll
        for (int r = 0; r < 7; r++) {
#pragma unroll
            for (int j = 0; j < 22; j++) {
                const int lo = (dwMin(r) > j - 18) ? dwMin(r) : j - 18;
                const int hi = (dwMax(r) < j - 3)  ? dwMax(r) : j - 3;
                if (lo <= hi) {
                    const unsigned long long v = vbu[rowb[r] + colb[j] + lane];
#pragma unroll
                    for (int dw = lo; dw <= hi; dw++) {
                        const int qi = j - 3 - dw;            // 0..15 (compile-time)
                        const int nb = nbBase(r) + dw - dwMin(r);
                        const float p = __shfl_sync(0xffffffffu, preg[nb], qi);
                        fma2(acc[qi], pk2(p), v);
                    }
                }
            }
        }

        // store this chunk's outputs
#pragma unroll
        for (int qi = 0; qi < 16; qi++) {
            const int q = qrow * kHW + qbase + qi;
            *reinterpret_cast<unsigned long long*>(
                obase + (size_t)q * kRow + c * kDC + lane * 2) = acc[qi];
        }
    }
}

extern "C" void kernel_launch(void* const* d_in, const int* in_sizes, int n_in,
                              void* d_out, int out_size)
{
    const float* levels = (const float*)d_in[0];
    // d_in[1] (non_local_mask) is a pure function of the fixed 32x32 geometry.
    float* out = (float*)d_out;

    cudaFuncSetAttribute(k1_scores,
                         cudaFuncAttributeMaxDynamicSharedMemorySize, kSmem1);
    cudaFuncSetAttribute(k2_out,
                         cudaFuncAttributeMaxDynamicSharedMemorySize, kSmem2);

    dim3 grid(kHW / kQR, kL, kB);   // (8, 6, 8)
    k1_scores<<<grid, 256, kSmem1>>>(levels);
    k2_out<<<grid, 256, kSmem2>>>(levels, out);
}